// round 13
// baseline (speedup 1.0000x reference)
#include <cuda_runtime.h>
#include <math.h>

#define BB 2
#define NN 512
#define DIMV 256
#define HH 8
#define DHV 32
#define SCALEV 0.17677669529663687f   // 32^-0.5

// ---------------- scratch (device globals; no allocation) ----------------
__device__ float g_q [BB*HH*NN*DHV];     // [b][h][i][d]
__device__ float g_k [BB*HH*NN*DHV];     // [b][h][j][d]
__device__ float g_v [BB*HH*NN*DHV];     // [b][h][j][d]
__device__ float g_qW[BB*NN*HH*256];     // [(b,i)][h][c]
__device__ float g_qk[BB*NN*HH*NN];      // [(b,i)][h][j]
__device__ float g_at[BB*NN*HH*NN];      // attn, same layout
__device__ float g_ae[BB*NN*HH*256];     // [(b,i)][h][c]
__device__ float g_ov[BB*NN*DIMV];       // [(b,i)][h*32+d]
__device__ float g_u [BB*NN*DIMV];       // [(b,i)][h*32+d]

// ---------------- cp.async helpers ----------------
__device__ __forceinline__ void cpa16(float* dst, const float* src) {
    unsigned s = (unsigned)__cvta_generic_to_shared(dst);
    asm volatile("cp.async.cg.shared.global [%0], [%1], 16;" :: "r"(s), "l"(src));
}
__device__ __forceinline__ void cp_commit() { asm volatile("cp.async.commit_group;"); }
template<int N> __device__ __forceinline__ void cp_wait() {
    asm volatile("cp.async.wait_group %0;" :: "n"(N));
}

// ================= K1: projections q,k,v (transposed per-head) =================
// grid (24 colchunks, 32 rowchunks), 256 thr, dyn smem 66560B
__global__ void k_proj(const float* __restrict__ nodes,
                       const float* __restrict__ Wq,  const float* __restrict__ bq,
                       const float* __restrict__ Wkv, const float* __restrict__ bkv) {
    extern __shared__ float sm[];
    float* sN = sm;            // [32][256]
    float* sW = sm + 32*256;   // [256][33]
    int cb = blockIdx.x, rb = blockIdx.y;
    int tid = threadIdx.x;
    int rowbase = rb*32;
    #pragma unroll 8
    for (int k = 0; k < 32; k++)
        sN[k*256 + tid] = nodes[(size_t)(rowbase + k)*256 + tid];
    int d = tid & 31, cw = tid >> 5;
    int col = cb*32 + d;
    const float* Wsrc; int ldw; int wcol;
    if (col < 256) { Wsrc = Wq;  ldw = 256; wcol = col; }
    else           { Wsrc = Wkv; ldw = 512; wcol = col - 256; }
    #pragma unroll 8
    for (int k = 0; k < 32; k++) {
        int c = k*8 + cw;
        sW[c*33 + d] = Wsrc[(size_t)c*ldw + wcol];
    }
    __syncthreads();
    int w = tid >> 5;
    float a0=0,a1=0,a2=0,a3=0;
    #pragma unroll 4
    for (int c = 0; c < 256; c++) {
        float wv = sW[c*33 + d];
        a0 += sN[ w      *256 + c]*wv;
        a1 += sN[(w + 8 )*256 + c]*wv;
        a2 += sN[(w + 16)*256 + c]*wv;
        a3 += sN[(w + 24)*256 + c]*wv;
    }
    float acc[4] = {a0,a1,a2,a3};
    float bias = (col < 256) ? bq[col] : bkv[col - 256];
    int sec = cb >> 3, hh = cb & 7;
    float* dst = (sec == 0) ? g_q : (sec == 1) ? g_k : g_v;
    #pragma unroll
    for (int k = 0; k < 4; k++) {
        int row = rowbase + w + k*8;
        int b = row >> 9, i = row & 511;
        dst[(((size_t)(b*8 + hh))*512 + i)*32 + d] = acc[k] + bias;
    }
}

// ================= K2: qW[b,i,h,c] = sum_d q[b,h,i,d]*We[c,h*32+d] =================
// grid (32 rowchunks, 8 heads), 256 thr
__global__ void k_qw(const float* __restrict__ We) {
    __shared__ float sW[32*257];   // [d][257 pitch] = We[c][h*32+d] transposed
    __shared__ float sq[32*32];    // [r][d]
    int rb = blockIdx.x, h = blockIdx.y;
    int tid = threadIdx.x;
    int d = tid & 31, cw = tid >> 5;
    #pragma unroll 8
    for (int k = 0; k < 32; k++) {
        int c = k*8 + cw;
        sW[d*257 + c] = We[(size_t)c*256 + h*32 + d];
    }
    #pragma unroll
    for (int k = 0; k < 4; k++) {
        int idx = k*256 + tid; int r = idx >> 5; int dd = idx & 31;
        int row = rb*32 + r; int b = row >> 9, i = row & 511;
        sq[r*32 + dd] = g_q[(((size_t)(b*8 + h))*512 + i)*32 + dd];
    }
    __syncthreads();
    int c = tid;
    for (int r = 0; r < 32; r++) {
        float acc = 0.f;
        #pragma unroll
        for (int dd = 0; dd < 32; dd++) acc += sq[r*32 + dd] * sW[dd*257 + c];
        int row = rb*32 + r;
        g_qW[(((size_t)row)*8 + h)*256 + c] = acc;
    }
}

// ================= K3: qk[b,i,h,j] = q_h[i]·k_h[j] =================
// grid (8 jt, 8 it, 16 bh), 256 thr
__global__ void k_qk() {
    __shared__ float Qs[64*33], Ks[64*33];
    int jt = blockIdx.x, it = blockIdx.y, bh = blockIdx.z;
    int tid = threadIdx.x;
    #pragma unroll
    for (int k = 0; k < 8; k++) {
        int idx = k*256 + tid; int r = idx >> 5, d = idx & 31;
        Qs[r*33 + d] = g_q[(((size_t)bh)*512 + it*64 + r)*32 + d];
        Ks[r*33 + d] = g_k[(((size_t)bh)*512 + jt*64 + r)*32 + d];
    }
    __syncthreads();
    int tx = tid & 15, ty = tid >> 4;
    float acc[4][4] = {};
    #pragma unroll 8
    for (int dd = 0; dd < 32; dd++) {
        float qr[4], kr[4];
        #pragma unroll
        for (int a = 0; a < 4; a++) qr[a] = Qs[(ty*4 + a)*33 + dd];
        #pragma unroll
        for (int a = 0; a < 4; a++) kr[a] = Ks[(tx*4 + a)*33 + dd];
        #pragma unroll
        for (int a = 0; a < 4; a++)
            #pragma unroll
            for (int b2 = 0; b2 < 4; b2++) acc[a][b2] += qr[a]*kr[b2];
    }
    int b = bh >> 3, h = bh & 7;
    #pragma unroll
    for (int a = 0; a < 4; a++) {
        int i = it*64 + ty*4 + a;
        size_t base = (((size_t)(b*512 + i))*8 + h)*512 + jt*64 + tx*4;
        #pragma unroll
        for (int b2 = 0; b2 < 4; b2++) g_qk[base + b2] = acc[a][b2];
    }
}

// ================= K4: fused edge passes (qe+softmax, then ae) =================
#define EPITCH 260
// grid 1024, 512 thr, dyn smem 157824B, occ 1/SM (L2 reuse for pass 2)
__global__ __launch_bounds__(512, 1) void k_passAB(const float* __restrict__ edges) {
    extern __shared__ float sm[];
    float* sE[2];
    sE[0] = sm;
    sE[1] = sm + 64*EPITCH;
    float* sqW = sm + 2*64*EPITCH;   // [8][260]
    float* sL  = sqW + 8*260;        // [8][512] : qk -> logits -> attn
    int bi = blockIdx.x; int tid = threadIdx.x;
    const float* Ebase = edges + ((size_t)bi)*512*256;

    #pragma unroll
    for (int k = 0; k < 4; k++) {
        int idx = k*512 + tid; int h = idx >> 8, c = idx & 255;
        sqW[h*260 + c] = g_qW[(((size_t)bi)*8 + h)*256 + c];
    }
    #pragma unroll
    for (int k = 0; k < 8; k++) {
        int idx = k*512 + tid; int h = idx >> 9, j = idx & 511;
        sL[h*512 + j] = g_qk[(((size_t)bi)*8 + h)*512 + j];
    }

    // tile loader: 64 rows x 256 floats
    auto load_tile = [&](int t, float* buf) {
        const float* src = Ebase + (size_t)t*64*256;
        #pragma unroll
        for (int k = 0; k < 8; k++) {
            int idx = k*512 + tid; int r = idx >> 6, c4 = idx & 63;
            cpa16(buf + r*EPITCH + c4*4, src + r*256 + c4*4);
        }
    };

    // ---------- phase 1: qe + logits ----------
    int h1 = tid & 7, jl = tid >> 3;
    load_tile(0, sE[0]); cp_commit();
    for (int t = 0; t < 8; t++) {
        float* buf = sE[t & 1];
        if (t < 7) { load_tile(t + 1, sE[(t + 1) & 1]); cp_commit(); cp_wait<1>(); }
        else       { cp_wait<0>(); }
        __syncthreads();
        const float4* er4 = (const float4*)(buf + jl*EPITCH);
        const float4* wr4 = (const float4*)(sqW + h1*260);
        float a0=0,a1=0,a2=0,a3=0;
        #pragma unroll 8
        for (int c = 0; c < 64; c++) {
            float4 e = er4[c], wv = wr4[c];
            a0 += e.x*wv.x; a1 += e.y*wv.y; a2 += e.z*wv.z; a3 += e.w*wv.w;
        }
        int j = t*64 + jl;
        sL[h1*512 + j] = (sL[h1*512 + j] + ((a0 + a1) + (a2 + a3))) * SCALEV;
        __syncthreads();
    }

    // ---------- softmax (warp w handles head w) ----------
    int w = tid >> 5, lane = tid & 31;
    if (w < 8) {
        float* row = sL + w*512;
        float v[16];
        #pragma unroll
        for (int k = 0; k < 16; k++) v[k] = row[lane + k*32];
        float m = v[0];
        #pragma unroll
        for (int k = 1; k < 16; k++) m = fmaxf(m, v[k]);
        #pragma unroll
        for (int o = 16; o > 0; o >>= 1) m = fmaxf(m, __shfl_xor_sync(0xffffffffu, m, o));
        float s = 0.f;
        #pragma unroll
        for (int k = 0; k < 16; k++) { v[k] = __expf(v[k] - m); s += v[k]; }
        #pragma unroll
        for (int o = 16; o > 0; o >>= 1) s += __shfl_xor_sync(0xffffffffu, s, o);
        float inv = 1.0f / s;
        size_t gbase = (((size_t)bi)*8 + w)*512;
        #pragma unroll
        for (int k = 0; k < 16; k++) {
            float p = v[k]*inv;
            row[lane + k*32] = p;
            g_at[gbase + lane + k*32] = p;
        }
    }
    __syncthreads();

    // ---------- phase 2: ae[h][c] = sum_j attn*E (edges re-read, L2-warm) ----------
    int h2 = tid >> 6, cg = tid & 63;
    float b0=0,b1=0,b2=0,b3=0;
    load_tile(0, sE[0]); cp_commit();
    for (int t = 0; t < 8; t++) {
        float* buf = sE[t & 1];
        if (t < 7) { load_tile(t + 1, sE[(t + 1) & 1]); cp_commit(); cp_wait<1>(); }
        else       { cp_wait<0>(); }
        __syncthreads();
        const float* arow = sL + h2*512 + t*64;
        #pragma unroll 8
        for (int j2 = 0; j2 < 64; j2++) {
            float a = arow[j2];
            float4 e = ((const float4*)(buf + j2*EPITCH))[cg];
            b0 += a*e.x; b1 += a*e.y; b2 += a*e.z; b3 += a*e.w;
        }
        __syncthreads();
    }
    float4 r4; r4.x=b0; r4.y=b1; r4.z=b2; r4.w=b3;
    ((float4*)(g_ae + (((size_t)bi)*8 + h2)*256))[cg] = r4;
}

// ================= K5: ov = attn @ v =================
// grid (8 itile, 8 h, 2 b), 256 thr
__global__ void k_outv() {
    __shared__ float sA[64*65];
    __shared__ float sV[64*33];
    int it = blockIdx.x, h = blockIdx.y, b = blockIdx.z;
    int tid = threadIdx.x;
    int ii = tid >> 2, dg = tid & 3, d0 = dg*8;
    float acc[8] = {};
    for (int jc = 0; jc < 8; jc++) {
        #pragma unroll
        for (int k = 0; k < 16; k++) {
            int idx = k*256 + tid; int r = idx >> 6, c = idx & 63;
            sA[r*65 + c] = g_at[(((size_t)(b*512 + it*64 + r))*8 + h)*512 + jc*64 + c];
        }
        #pragma unroll
        for (int k = 0; k < 8; k++) {
            int idx = k*256 + tid; int r = idx >> 5, c = idx & 31;
            sV[r*33 + c] = g_v[(((size_t)(b*8 + h))*512 + jc*64 + r)*32 + c];
        }
        __syncthreads();
        #pragma unroll 4
        for (int jl = 0; jl < 64; jl++) {
            float a = sA[ii*65 + jl];
            #pragma unroll
            for (int dd = 0; dd < 8; dd++) acc[dd] += a * sV[jl*33 + d0 + dd];
        }
        __syncthreads();
    }
    size_t obase = ((size_t)(b*512 + it*64 + ii))*256 + h*32 + d0;
    #pragma unroll
    for (int dd = 0; dd < 8; dd++) g_ov[obase + dd] = acc[dd];
}

// ================= K6: u = ov + ae@We_h + be =================
// grid (32 rowchunks, 8 h), 256 thr, dyn smem 66688B
__global__ void k_oe(const float* __restrict__ We, const float* __restrict__ be) {
    extern __shared__ float sm[];
    float* sW = sm;            // [256][33]  We[:, h*32..h*32+32]
    float* sa = sm + 256*33;   // [32][257]
    int rb = blockIdx.x, h = blockIdx.y;
    int tid = threadIdx.x;
    int d = tid & 31, cw = tid >> 5;
    #pragma unroll 8
    for (int k = 0; k < 32; k++) {
        int c = k*8 + cw;
        sW[c*33 + d] = We[(size_t)c*256 + h*32 + d];
    }
    #pragma unroll 8
    for (int k = 0; k < 32; k++)
        sa[k*257 + tid] = g_ae[(((size_t)(rb*32 + k))*8 + h)*256 + tid];
    __syncthreads();
    int w = tid >> 5;
    float a0=0,a1=0,a2=0,a3=0;
    #pragma unroll 4
    for (int c = 0; c < 256; c++) {
        float wv = sW[c*33 + d];
        a0 += sa[ w      *257 + c]*wv;
        a1 += sa[(w + 8 )*257 + c]*wv;
        a2 += sa[(w + 16)*257 + c]*wv;
        a3 += sa[(w + 24)*257 + c]*wv;
    }
    float acc[4] = {a0,a1,a2,a3};
    float bias = be[h*32 + d];
    #pragma unroll
    for (int k = 0; k < 4; k++) {
        size_t o = ((size_t)(rb*32 + w + k*8))*256 + h*32 + d;
        g_u[o] = acc[k] + bias + g_ov[o];
    }
}

// ================= K7: out = u @ Wo + bo =================
// grid (8 colchunks, 32 rowchunks), 256 thr, dyn smem 66688B
__global__ void k_final(const float* __restrict__ Wo, const float* __restrict__ bo,
                        float* __restrict__ out) {
    extern __shared__ float sm[];
    float* sW = sm;            // [256][33]
    float* su = sm + 256*33;   // [32][257]
    int cb = blockIdx.x, rb = blockIdx.y;
    int tid = threadIdx.x;
    int d = tid & 31, cw = tid >> 5;
    #pragma unroll 8
    for (int k = 0; k < 32; k++) {
        int c = k*8 + cw;
        sW[c*33 + d] = Wo[(size_t)c*256 + cb*32 + d];
    }
    #pragma unroll 8
    for (int k = 0; k < 32; k++)
        su[k*257 + tid] = g_u[((size_t)(rb*32 + k))*256 + tid];
    __syncthreads();
    int w = tid >> 5;
    float a0=0,a1=0,a2=0,a3=0;
    #pragma unroll 4
    for (int c = 0; c < 256; c++) {
        float wv = sW[c*33 + d];
        a0 += su[ w      *257 + c]*wv;
        a1 += su[(w + 8 )*257 + c]*wv;
        a2 += su[(w + 16)*257 + c]*wv;
        a3 += su[(w + 24)*257 + c]*wv;
    }
    float acc[4] = {a0,a1,a2,a3};
    float bias = bo[cb*32 + d];
    #pragma unroll
    for (int k = 0; k < 4; k++)
        out[((size_t)(rb*32 + w + k*8))*256 + cb*32 + d] = acc[k] + bias;
}

// ================= launch =================
extern "C" void kernel_launch(void* const* d_in, const int* in_sizes, int n_in,
                              void* d_out, int out_size) {
    const float* nodes = (const float*)d_in[0];
    const float* edges = (const float*)d_in[1];
    const float* Wq    = (const float*)d_in[2];
    const float* bq    = (const float*)d_in[3];
    const float* Wkv   = (const float*)d_in[4];
    const float* bkv   = (const float*)d_in[5];
    const float* We    = (const float*)d_in[6];
    const float* be    = (const float*)d_in[7];
    const float* Wo    = (const float*)d_in[8];
    const float* bo    = (const float*)d_in[9];
    float* out = (float*)d_out;

    cudaFuncSetAttribute(k_proj,   cudaFuncAttributeMaxDynamicSharedMemorySize, 66560);
    cudaFuncSetAttribute(k_passAB, cudaFuncAttributeMaxDynamicSharedMemorySize, 157824);
    cudaFuncSetAttribute(k_oe,     cudaFuncAttributeMaxDynamicSharedMemorySize, 66688);
    cudaFuncSetAttribute(k_final,  cudaFuncAttributeMaxDynamicSharedMemorySize, 66688);

    k_proj  <<<dim3(24, 32),    256, 66560>>>(nodes, Wq, bq, Wkv, bkv);
    k_qw    <<<dim3(32, 8),     256>>>(We);
    k_qk    <<<dim3(8, 8, 16),  256>>>();
    k_passAB<<<1024,            512, 157824>>>(edges);
    k_outv  <<<dim3(8, 8, 2),   256>>>();
    k_oe    <<<dim3(32, 8),     256, 66688>>>(We, be);
    k_final <<<dim3(8, 32),     256, 66688>>>(Wo, bo, out);
}

// round 14
// speedup vs baseline: 1.5606x; 1.5606x over previous
#include <cuda_runtime.h>
#include <math.h>

#define BB 2
#define NN 512
#define DIMV 256
#define HH 8
#define DHV 32
#define SCALEV 0.17677669529663687f   // 32^-0.5
#define SLP 516                        // sL pitch (floats): mult of 4, bank stride 4

// ---------------- scratch (device globals; no allocation) ----------------
__device__ float g_q [BB*HH*NN*DHV];     // [b][h][i][d]
__device__ float g_k [BB*HH*NN*DHV];     // [b][h][j][d]
__device__ float g_v [BB*HH*NN*DHV];     // [b][h][j][d]
__device__ float g_qW[BB*NN*HH*256];     // [(b,i)][h][c]
__device__ float g_qk[BB*NN*HH*NN];      // [(b,i)][h][j]
__device__ float g_at[BB*NN*HH*NN];      // attn, same layout
__device__ float g_ae[BB*NN*HH*256];     // [(b,i)][h][c]
__device__ float g_ov[BB*NN*DIMV];       // [(b,i)][h*32+d]
__device__ float g_u [BB*NN*DIMV];       // [(b,i)][h*32+d]

// ---------------- packed f32x2 helpers ----------------
__device__ __forceinline__ void ffma2(unsigned long long& d,
                                      unsigned long long a, unsigned long long b) {
    asm("fma.rn.f32x2 %0, %1, %2, %0;" : "+l"(d) : "l"(a), "l"(b));
}
__device__ __forceinline__ unsigned long long pack2(float x) {
    unsigned long long r;
    asm("mov.b64 %0, {%1, %1};" : "=l"(r) : "f"(x));
    return r;
}
__device__ __forceinline__ void unpack2(unsigned long long v, float& lo, float& hi) {
    asm("mov.b64 {%0, %1}, %2;" : "=f"(lo), "=f"(hi) : "l"(v));
}

// ================= K1: projections q,k,v (transposed per-head) =================
__global__ void k_proj(const float* __restrict__ nodes,
                       const float* __restrict__ Wq,  const float* __restrict__ bq,
                       const float* __restrict__ Wkv, const float* __restrict__ bkv) {
    extern __shared__ float sm[];
    float* sN = sm;            // [32][256]
    float* sW = sm + 32*256;   // [256][33]
    int cb = blockIdx.x, rb = blockIdx.y;
    int tid = threadIdx.x;
    int rowbase = rb*32;
    #pragma unroll 8
    for (int k = 0; k < 32; k++)
        sN[k*256 + tid] = nodes[(size_t)(rowbase + k)*256 + tid];
    int d = tid & 31, cw = tid >> 5;
    int col = cb*32 + d;
    const float* Wsrc; int ldw; int wcol;
    if (col < 256) { Wsrc = Wq;  ldw = 256; wcol = col; }
    else           { Wsrc = Wkv; ldw = 512; wcol = col - 256; }
    #pragma unroll 8
    for (int k = 0; k < 32; k++) {
        int c = k*8 + cw;
        sW[c*33 + d] = Wsrc[(size_t)c*ldw + wcol];
    }
    __syncthreads();
    int w = tid >> 5;
    float a0=0,a1=0,a2=0,a3=0;
    #pragma unroll 4
    for (int c = 0; c < 256; c++) {
        float wv = sW[c*33 + d];
        a0 += sN[ w      *256 + c]*wv;
        a1 += sN[(w + 8 )*256 + c]*wv;
        a2 += sN[(w + 16)*256 + c]*wv;
        a3 += sN[(w + 24)*256 + c]*wv;
    }
    float acc[4] = {a0,a1,a2,a3};
    float bias = (col < 256) ? bq[col] : bkv[col - 256];
    int sec = cb >> 3, hh = cb & 7;
    float* dst = (sec == 0) ? g_q : (sec == 1) ? g_k : g_v;
    #pragma unroll
    for (int k = 0; k < 4; k++) {
        int row = rowbase + w + k*8;
        int b = row >> 9, i = row & 511;
        dst[(((size_t)(b*8 + hh))*512 + i)*32 + d] = acc[k] + bias;
    }
}

// ================= K2: qW[b,i,h,c] = sum_d q[b,h,i,d]*We[c,h*32+d] =================
__global__ void k_qw(const float* __restrict__ We) {
    __shared__ float sW[32*257];
    __shared__ float sq[32*32];
    int rb = blockIdx.x, h = blockIdx.y;
    int tid = threadIdx.x;
    int d = tid & 31, cw = tid >> 5;
    #pragma unroll 8
    for (int k = 0; k < 32; k++) {
        int c = k*8 + cw;
        sW[d*257 + c] = We[(size_t)c*256 + h*32 + d];
    }
    #pragma unroll
    for (int k = 0; k < 4; k++) {
        int idx = k*256 + tid; int r = idx >> 5; int dd = idx & 31;
        int row = rb*32 + r; int b = row >> 9, i = row & 511;
        sq[r*32 + dd] = g_q[(((size_t)(b*8 + h))*512 + i)*32 + dd];
    }
    __syncthreads();
    int c = tid;
    for (int r = 0; r < 32; r++) {
        float acc = 0.f;
        #pragma unroll
        for (int dd = 0; dd < 32; dd++) acc += sq[r*32 + dd] * sW[dd*257 + c];
        int row = rb*32 + r;
        g_qW[(((size_t)row)*8 + h)*256 + c] = acc;
    }
}

// ================= K3: qk[b,i,h,j] = q_h[i]·k_h[j] =================
__global__ void k_qk() {
    __shared__ float Qs[64*33], Ks[64*33];
    int jt = blockIdx.x, it = blockIdx.y, bh = blockIdx.z;
    int tid = threadIdx.x;
    #pragma unroll
    for (int k = 0; k < 8; k++) {
        int idx = k*256 + tid; int r = idx >> 5, d = idx & 31;
        Qs[r*33 + d] = g_q[(((size_t)bh)*512 + it*64 + r)*32 + d];
        Ks[r*33 + d] = g_k[(((size_t)bh)*512 + jt*64 + r)*32 + d];
    }
    __syncthreads();
    int tx = tid & 15, ty = tid >> 4;
    float acc[4][4] = {};
    #pragma unroll 8
    for (int dd = 0; dd < 32; dd++) {
        float qr[4], kr[4];
        #pragma unroll
        for (int a = 0; a < 4; a++) qr[a] = Qs[(ty*4 + a)*33 + dd];
        #pragma unroll
        for (int a = 0; a < 4; a++) kr[a] = Ks[(tx*4 + a)*33 + dd];
        #pragma unroll
        for (int a = 0; a < 4; a++)
            #pragma unroll
            for (int b2 = 0; b2 < 4; b2++) acc[a][b2] += qr[a]*kr[b2];
    }
    int b = bh >> 3, h = bh & 7;
    #pragma unroll
    for (int a = 0; a < 4; a++) {
        int i = it*64 + ty*4 + a;
        size_t base = (((size_t)(b*512 + i))*8 + h)*512 + jt*64 + tx*4;
        #pragma unroll
        for (int b2 = 0; b2 < 4; b2++) g_qk[base + b2] = acc[a][b2];
    }
}

// ================= K4 v2: fused edge passes — register qW + direct LDG =================
// grid 1024 (one per (b,i)), 512 thr, dyn smem 82048B
// phase1: sim[h][j] = sum_c E[j][c]*qW[h][c]   (E from DRAM, qW in regs, shfl-reduce)
// phase2: ae[h][c]  = sum_j attn[h][j]*E[j][c] (E from L2, coalesced, smem reduce)
__global__ __launch_bounds__(512, 1) void k_passAB(const float* __restrict__ edges) {
    extern __shared__ float sm[];
    float* sL   = sm;              // [8][SLP]  logits -> attn
    float* sRed = sm + 8*SLP;      // [8 jsp][8 h][64 cch][4] = 16384 floats
    int bi = blockIdx.x, tid = threadIdx.x;
    const float* Eb = edges + (size_t)bi*512*256;

    // preload qk into sL
    #pragma unroll
    for (int k = 0; k < 8; k++) {
        int idx = k*512 + tid; int h = idx >> 9, j = idx & 511;
        sL[h*SLP + j] = g_qk[(((size_t)bi)*8 + h)*512 + j];
    }

    // ---------- phase 1 ----------
    {
        int csplit = tid & 15;          // 16 channel-splits of 16 channels
        int hs     = (tid >> 4) & 1;    // head-half (4 heads each)
        int jl     = tid >> 5;          // warp id = row group (32 rows)

        // qW slice in registers: 4 heads x 16 channels = 32 f32x2
        unsigned long long qw[4][8];
        const float* qWb = g_qW + ((size_t)bi)*8*256;
        #pragma unroll
        for (int a = 0; a < 4; a++) {
            const unsigned long long* p =
                (const unsigned long long*)(qWb + (size_t)(hs*4 + a)*256 + csplit*16);
            #pragma unroll
            for (int q = 0; q < 8; q++) qw[a][q] = p[q];
        }
        __syncthreads();   // qk preload complete

        const char* rowp = (const char*)(Eb + (size_t)(jl*32)*256 + csplit*16);
        ulonglong2 e[4];
        #pragma unroll
        for (int q = 0; q < 4; q++) e[q] = ((const ulonglong2*)rowp)[q];

        for (int t = 0; t < 32; t++) {
            const char* nxt = rowp + 1024;
            ulonglong2 en[4];
            #pragma unroll
            for (int q = 0; q < 4; q++) en[q] = e[q];
            if (t < 31) {
                #pragma unroll
                for (int q = 0; q < 4; q++) en[q] = ((const ulonglong2*)nxt)[q];
            }
            float s[4];
            #pragma unroll
            for (int a = 0; a < 4; a++) {
                unsigned long long acc = 0ull;
                #pragma unroll
                for (int q = 0; q < 4; q++) {
                    ffma2(acc, e[q].x, qw[a][2*q]);
                    ffma2(acc, e[q].y, qw[a][2*q + 1]);
                }
                float lo, hi; unpack2(acc, lo, hi);
                s[a] = lo + hi;
            }
            // reduce over 16 csplit lanes (stays within 16-lane half)
            #pragma unroll
            for (int a = 0; a < 4; a++) {
                s[a] += __shfl_xor_sync(0xffffffffu, s[a], 1);
                s[a] += __shfl_xor_sync(0xffffffffu, s[a], 2);
                s[a] += __shfl_xor_sync(0xffffffffu, s[a], 4);
                s[a] += __shfl_xor_sync(0xffffffffu, s[a], 8);
            }
            int j = jl*32 + t;
            if (csplit < 4) {
                int h = hs*4 + csplit;
                sL[h*SLP + j] = (sL[h*SLP + j] + s[csplit]) * SCALEV;
            }
            #pragma unroll
            for (int q = 0; q < 4; q++) e[q] = en[q];
            rowp = nxt;
        }
    }
    __syncthreads();

    // ---------- softmax (warp w handles head w) ----------
    {
        int w = tid >> 5, lane = tid & 31;
        if (w < 8) {
            float* row = sL + w*SLP;
            float v[16];
            #pragma unroll
            for (int k = 0; k < 16; k++) v[k] = row[lane + k*32];
            float m = v[0];
            #pragma unroll
            for (int k = 1; k < 16; k++) m = fmaxf(m, v[k]);
            #pragma unroll
            for (int o = 16; o > 0; o >>= 1) m = fmaxf(m, __shfl_xor_sync(0xffffffffu, m, o));
            float s = 0.f;
            #pragma unroll
            for (int k = 0; k < 16; k++) { v[k] = __expf(v[k] - m); s += v[k]; }
            #pragma unroll
            for (int o = 16; o > 0; o >>= 1) s += __shfl_xor_sync(0xffffffffu, s, o);
            float inv = 1.0f / s;
            size_t gbase = (((size_t)bi)*8 + w)*512;
            #pragma unroll
            for (int k = 0; k < 16; k++) {
                float p = v[k]*inv;
                row[lane + k*32] = p;
                g_at[gbase + lane + k*32] = p;   // k_outv consumes this
            }
        }
    }
    __syncthreads();

    // ---------- phase 2: ae (E re-read from L2, coalesced) ----------
    {
        int cch = tid & 63;     // float4 channel chunk
        int jsp = tid >> 6;     // 8 j-splits of 64 rows
        unsigned long long acc[8][2];
        #pragma unroll
        for (int h = 0; h < 8; h++) { acc[h][0] = 0ull; acc[h][1] = 0ull; }

        const char* rp = (const char*)(Eb + (size_t)(jsp*64)*256 + cch*4);
        for (int t = 0; t < 64; t += 4) {
            int j0 = jsp*64 + t;
            float4 at[8];
            #pragma unroll
            for (int h = 0; h < 8; h++)
                at[h] = *(const float4*)&sL[h*SLP + j0];
            #pragma unroll
            for (int r = 0; r < 4; r++) {
                ulonglong2 ev = *(const ulonglong2*)(rp + (size_t)(t + r)*1024);
                #pragma unroll
                for (int h = 0; h < 8; h++) {
                    float av = (r == 0) ? at[h].x : (r == 1) ? at[h].y
                             : (r == 2) ? at[h].z : at[h].w;
                    unsigned long long a2 = pack2(av);
                    ffma2(acc[h][0], a2, ev.x);
                    ffma2(acc[h][1], a2, ev.y);
                }
            }
        }
        // stage partials for cross-jsp reduction
        #pragma unroll
        for (int h = 0; h < 8; h++) {
            float4 v;
            unpack2(acc[h][0], v.x, v.y);
            unpack2(acc[h][1], v.z, v.w);
            *(float4*)&sRed[(((size_t)(jsp*8 + h))*64 + cch)*4] = v;
        }
    }
    __syncthreads();
    {
        int h = tid >> 6, cc = tid & 63;
        float4 s = make_float4(0.f, 0.f, 0.f, 0.f);
        #pragma unroll
        for (int js = 0; js < 8; js++) {
            float4 p = *(const float4*)&sRed[(((size_t)(js*8 + h))*64 + cc)*4];
            s.x += p.x; s.y += p.y; s.z += p.z; s.w += p.w;
        }
        *(float4*)&g_ae[(((size_t)bi)*8 + h)*256 + cc*4] = s;
    }
}

// ================= K5: ov = attn @ v =================
__global__ void k_outv() {
    __shared__ float sA[64*65];
    __shared__ float sV[64*33];
    int it = blockIdx.x, h = blockIdx.y, b = blockIdx.z;
    int tid = threadIdx.x;
    int ii = tid >> 2, dg = tid & 3, d0 = dg*8;
    float acc[8] = {};
    for (int jc = 0; jc < 8; jc++) {
        #pragma unroll
        for (int k = 0; k < 16; k++) {
            int idx = k*256 + tid; int r = idx >> 6, c = idx & 63;
            sA[r*65 + c] = g_at[(((size_t)(b*512 + it*64 + r))*8 + h)*512 + jc*64 + c];
        }
        #pragma unroll
        for (int k = 0; k < 8; k++) {
            int idx = k*256 + tid; int r = idx >> 5, c = idx & 31;
            sV[r*33 + c] = g_v[(((size_t)(b*8 + h))*512 + jc*64 + r)*32 + c];
        }
        __syncthreads();
        #pragma unroll 4
        for (int jl = 0; jl < 64; jl++) {
            float a = sA[ii*65 + jl];
            #pragma unroll
            for (int dd = 0; dd < 8; dd++) acc[dd] += a * sV[jl*33 + d0 + dd];
        }
        __syncthreads();
    }
    size_t obase = ((size_t)(b*512 + it*64 + ii))*256 + h*32 + d0;
    #pragma unroll
    for (int dd = 0; dd < 8; dd++) g_ov[obase + dd] = acc[dd];
}

// ================= K6: u = ov + ae@We_h + be =================
__global__ void k_oe(const float* __restrict__ We, const float* __restrict__ be) {
    extern __shared__ float sm[];
    float* sW = sm;            // [256][33]
    float* sa = sm + 256*33;   // [32][257]
    int rb = blockIdx.x, h = blockIdx.y;
    int tid = threadIdx.x;
    int d = tid & 31, cw = tid >> 5;
    #pragma unroll 8
    for (int k = 0; k < 32; k++) {
        int c = k*8 + cw;
        sW[c*33 + d] = We[(size_t)c*256 + h*32 + d];
    }
    #pragma unroll 8
    for (int k = 0; k < 32; k++)
        sa[k*257 + tid] = g_ae[(((size_t)(rb*32 + k))*8 + h)*256 + tid];
    __syncthreads();
    int w = tid >> 5;
    float a0=0,a1=0,a2=0,a3=0;
    #pragma unroll 4
    for (int c = 0; c < 256; c++) {
        float wv = sW[c*33 + d];
        a0 += sa[ w      *257 + c]*wv;
        a1 += sa[(w + 8 )*257 + c]*wv;
        a2 += sa[(w + 16)*257 + c]*wv;
        a3 += sa[(w + 24)*257 + c]*wv;
    }
    float acc[4] = {a0,a1,a2,a3};
    float bias = be[h*32 + d];
    #pragma unroll
    for (int k = 0; k < 4; k++) {
        size_t o = ((size_t)(rb*32 + w + k*8))*256 + h*32 + d;
        g_u[o] = acc[k] + bias + g_ov[o];
    }
}

// ================= K7: out = u @ Wo + bo =================
__global__ void k_final(const float* __restrict__ Wo, const float* __restrict__ bo,
                        float* __restrict__ out) {
    extern __shared__ float sm[];
    float* sW = sm;            // [256][33]
    float* su = sm + 256*33;   // [32][257]
    int cb = blockIdx.x, rb = blockIdx.y;
    int tid = threadIdx.x;
    int d = tid & 31, cw = tid >> 5;
    #pragma unroll 8
    for (int k = 0; k < 32; k++) {
        int c = k*8 + cw;
        sW[c*33 + d] = Wo[(size_t)c*256 + cb*32 + d];
    }
    #pragma unroll 8
    for (int k = 0; k < 32; k++)
        su[k*257 + tid] = g_u[((size_t)(rb*32 + k))*256 + tid];
    __syncthreads();
    int w = tid >> 5;
    float a0=0,a1=0,a2=0,a3=0;
    #pragma unroll 4
    for (int c = 0; c < 256; c++) {
        float wv = sW[c*33 + d];
        a0 += su[ w      *257 + c]*wv;
        a1 += su[(w + 8 )*257 + c]*wv;
        a2 += su[(w + 16)*257 + c]*wv;
        a3 += su[(w + 24)*257 + c]*wv;
    }
    float acc[4] = {a0,a1,a2,a3};
    float bias = bo[cb*32 + d];
    #pragma unroll
    for (int k = 0; k < 4; k++)
        out[((size_t)(rb*32 + w + k*8))*256 + cb*32 + d] = acc[k] + bias;
}

// ================= launch =================
extern "C" void kernel_launch(void* const* d_in, const int* in_sizes, int n_in,
                              void* d_out, int out_size) {
    const float* nodes = (const float*)d_in[0];
    const float* edges = (const float*)d_in[1];
    const float* Wq    = (const float*)d_in[2];
    const float* bq    = (const float*)d_in[3];
    const float* Wkv   = (const float*)d_in[4];
    const float* bkv   = (const float*)d_in[5];
    const float* We    = (const float*)d_in[6];
    const float* be    = (const float*)d_in[7];
    const float* Wo    = (const float*)d_in[8];
    const float* bo    = (const float*)d_in[9];
    float* out = (float*)d_out;

    const int SMEM_PASS = (8*SLP + 16384) * 4;   // 82048

    cudaFuncSetAttribute(k_proj,   cudaFuncAttributeMaxDynamicSharedMemorySize, 66560);
    cudaFuncSetAttribute(k_passAB, cudaFuncAttributeMaxDynamicSharedMemorySize, SMEM_PASS);
    cudaFuncSetAttribute(k_oe,     cudaFuncAttributeMaxDynamicSharedMemorySize, 66688);
    cudaFuncSetAttribute(k_final,  cudaFuncAttributeMaxDynamicSharedMemorySize, 66688);

    k_proj  <<<dim3(24, 32),    256, 66560>>>(nodes, Wq, bq, Wkv, bkv);
    k_qw    <<<dim3(32, 8),     256>>>(We);
    k_qk    <<<dim3(8, 8, 16),  256>>>();
    k_passAB<<<1024,            512, SMEM_PASS>>>(edges);
    k_outv  <<<dim3(8, 8, 2),   256>>>();
    k_oe    <<<dim3(32, 8),     256, 66688>>>(We, be);
    k_final <<<dim3(8, 32),     256, 66688>>>(Wo, bo, out);
}